// round 14
// baseline (speedup 1.0000x reference)
#include <cuda_runtime.h>
#include <cuda_bf16.h>
#include <cuda_pipeline.h>
#include <mma.h>
#include <cstdint>

using namespace nvcuda;

// Problem constants
#define NL    6
#define DIMV  40
#define ADIMV 20
#define HHV   128
#define DINV  276
#define BATCH 131072
#define CLIPV 2.0f

#define TB 128
#define NT 512
#define ZP 44

// pitches
#define PA 136      // activation tile pitch (bf16 elems)
#define PW 136      // weight tile pitch (bf16 elems)
#define PCH 68      // heads C staging pitch (f32)
#define PH 72       // heads weight pitch (bf16)

#define ALO (128*PA)        // act lo-tile element offset

// weight image element counts per layer
#define E_ZA  (2*32*PA)     // 8704   (hi32|lo32)
#define E_C   (2*128*PW)    // 34816  (2 chunks of [hi64|lo64])
#define E_HD  (2*128*PH)    // 18432  (2 chunks of [hi64|lo64])

// chunk sizes
#define CHW_ELEM (128*PW)
#define CHH_ELEM (128*PH)
#define CB_MLP (CHW_ELEM*2)
#define CB_ZA  (E_ZA*2)
#define CB_HD  (CHH_ELEM*2)

#define WBUF_B 34816

// ---- flow kernel SMEM layout (bytes) ----
#define SM_ACT  0
#define SM_WB   (2*128*PA*2)                  // 69632
#define SM_CBH  (SM_WB + 2*WBUF_B)            // 139264
#define SM_ZT   (SM_CBH + 128*PCH*4)          // 174080
#define SM_LDET (SM_ZT + TB*ZP*4)             // 196608
#define SM_IDX  (SM_LDET + TB*4)              // 197120
#define SMEM_TOTAL (SM_IDX + 4*NL*ADIMV*4)    // 199040

// ---- pre kernel SMEM layout ----
#define PSM_CTX 0
#define PSM_TE  (2*128*PA*2)
#define PSM_WB  (2*2*128*PA*2)
#define SMEM_PRE (PSM_WB + 2*WBUF_B)          // 208896

typedef __nv_bfloat16 bf16;

__device__ __align__(16) bf16 g_Wza[NL * E_ZA];
__device__ __align__(16) bf16 g_Wc [NL * E_C];
__device__ __align__(16) bf16 g_Wt_[NL * E_C];
__device__ __align__(16) bf16 g_W2 [NL * E_C];
__device__ __align__(16) bf16 g_W3 [NL * E_C];
__device__ __align__(16) bf16 g_Whd[NL * E_HD];

__device__ float g_U[(size_t)NL * BATCH * HHV];

__device__ __forceinline__ void split_store(bf16* hi_p, bf16* lo_p, float v) {
    bf16 h = __float2bfloat16(v);
    bf16 lo = __float2bfloat16(v - __bfloat162float(h));
    *hi_p = h; *lo_p = lo;
}

__global__ void prep_weights(const float* __restrict__ W1,
                             const float* __restrict__ W2,
                             const float* __restrict__ W3,
                             const float* __restrict__ Ws,
                             const float* __restrict__ Wt)
{
    int stride = gridDim.x * blockDim.x;
    int tid0 = blockIdx.x * blockDim.x + threadIdx.x;

    for (int t = tid0; t < NL * 32 * PA; t += stride) {
        int c = t % PA, k = (t / PA) % 32, l = t / (PA * 32);
        float v = (k < ADIMV && c < HHV) ? W1[((long long)l * DINV + k) * HHV + c] : 0.0f;
        bf16* base = g_Wza + (size_t)l * E_ZA;
        split_store(base + k * PA + c, base + 32 * PA + k * PA + c, v);
    }
    for (int t = tid0; t < NL * 128 * PW; t += stride) {
        int c = t % PW, k = (t / PW) % 128, l = t / (PW * 128);
        float vc = 0.f, vt = 0.f, v2 = 0.f, v3 = 0.f;
        if (c < HHV) {
            vc = W1[((long long)l * DINV + ADIMV + k) * HHV + c];
            vt = W1[((long long)l * DINV + ADIMV + HHV + k) * HHV + c];
            v2 = W2[((long long)l * HHV + k) * HHV + c];
            v3 = W3[((long long)l * HHV + k) * HHV + c];
        }
        int chunk = k >> 6, kr = k & 63;
        size_t o_hi = (size_t)l * E_C + (size_t)chunk * CHW_ELEM + (size_t)kr * PW + c;
        size_t o_lo = o_hi + (size_t)64 * PW;
        split_store(g_Wc + o_hi,  g_Wc + o_lo,  vc);
        split_store(g_Wt_ + o_hi, g_Wt_ + o_lo, vt);
        split_store(g_W2 + o_hi,  g_W2 + o_lo,  v2);
        split_store(g_W3 + o_hi,  g_W3 + o_lo,  v3);
    }
    for (int t = tid0; t < NL * 128 * PH; t += stride) {
        int c = t % PH, k = (t / PH) % 128, l = t / (PH * 128);
        float v = 0.0f;
        if (c < ADIMV)           v = Ws[((long long)l * HHV + k) * ADIMV + c];
        else if (c < 2 * ADIMV)  v = Wt[((long long)l * HHV + k) * ADIMV + (c - ADIMV)];
        int chunk = k >> 6, kr = k & 63;
        size_t o_hi = (size_t)l * E_HD + (size_t)chunk * CHH_ELEM + (size_t)kr * PH + c;
        split_store(g_Whd + o_hi, g_Whd + o_hi + 64 * PH, v);
    }
}

__device__ __forceinline__ float silu_f(float v) { return v / (1.0f + __expf(-v)); }

__device__ __forceinline__ void cpa(void* dst, const void* src, int bytes, int tid) {
    char* d = (char*)dst;
    const char* s = (const char*)src;
    for (int i = tid * 16; i < bytes; i += NT * 16)
        __pipeline_memcpy_async(d + i, s + i, 16);
    __pipeline_commit();
}

__device__ __forceinline__ uint32_t smem_u32(const void* p) {
    uint32_t a;
    asm("{ .reg .u64 t; cvta.to.shared.u64 t, %1; cvt.u32.u64 %0, t; }" : "=r"(a) : "l"(p));
    return a;
}

// ---------------- raw mma.sync helpers (flow kernel) ----------------
__device__ __forceinline__ void ldm4(uint32_t* d, uint32_t a) {
    asm volatile("ldmatrix.sync.aligned.m8n8.x4.shared.b16 {%0,%1,%2,%3}, [%4];"
                 : "=r"(d[0]), "=r"(d[1]), "=r"(d[2]), "=r"(d[3]) : "r"(a));
}
__device__ __forceinline__ void ldm4t(uint32_t* d, uint32_t a) {
    asm volatile("ldmatrix.sync.aligned.m8n8.x4.trans.shared.b16 {%0,%1,%2,%3}, [%4];"
                 : "=r"(d[0]), "=r"(d[1]), "=r"(d[2]), "=r"(d[3]) : "r"(a));
}
__device__ __forceinline__ void mmab(float* c, const uint32_t* a, const uint32_t* b) {
    asm volatile(
        "mma.sync.aligned.m16n8k16.row.col.f32.bf16.bf16.f32 "
        "{%0,%1,%2,%3}, {%4,%5,%6,%7}, {%8,%9}, {%0,%1,%2,%3};"
        : "+f"(c[0]), "+f"(c[1]), "+f"(c[2]), "+f"(c[3])
        : "r"(a[0]), "r"(a[1]), "r"(a[2]), "r"(a[3]), "r"(b[0]), "r"(b[1]));
}

// 3-term split GEMM on a 32x32 warp tile over one staged weight chunk.
// aHu: act hi smem byte addr (chunk k-origin pre-added); dAL: hi->lo byte delta.
// bHu: weight hi chunk smem byte addr; dBL: hi->lo byte delta; bpitch elems.
__device__ __forceinline__ void gemm32(uint32_t aHu, uint32_t dAL,
                                       uint32_t bHu, uint32_t dBL,
                                       int ksteps, int bpitch,
                                       float (&acc)[2][2][2][4],
                                       int lane, int row0, int col0)
{
    const int arow = lane & 15, akk = (lane >> 4) * 8;
    const int bkr = (lane & 7) + ((lane >> 3) & 1) * 8, bnc = (lane >> 4) * 8;
    for (int ks = 0; ks < ksteps; ++ks) {
        uint32_t aF[2][2][4], bF[2][2][4];   // [hi/lo][i or j][4]
#pragma unroll
        for (int i = 0; i < 2; ++i) {
            uint32_t ad = aHu + (uint32_t)(((row0 + 16 * i + arow) * PA + ks * 16 + akk) * 2);
            ldm4(aF[0][i], ad);
            ldm4(aF[1][i], ad + dAL);
        }
#pragma unroll
        for (int j = 0; j < 2; ++j) {
            uint32_t bd = bHu + (uint32_t)(((ks * 16 + bkr) * bpitch + col0 + 16 * j + bnc) * 2);
            ldm4t(bF[0][j], bd);
            ldm4t(bF[1][j], bd + dBL);
        }
#pragma unroll
        for (int i = 0; i < 2; ++i)
#pragma unroll
            for (int j = 0; j < 2; ++j)
#pragma unroll
                for (int nb = 0; nb < 2; ++nb) {
                    mmab(acc[i][j][nb], aF[0][i], &bF[0][j][2 * nb]);  // HH
                    mmab(acc[i][j][nb], aF[0][i], &bF[1][j][2 * nb]);  // HL
                    mmab(acc[i][j][nb], aF[1][i], &bF[0][j][2 * nb]);  // LH
                }
    }
}

// register-domain epilogue: bias + silu + hi/lo split -> act tiles directly
__device__ __forceinline__ void epi(float (&acc)[2][2][2][4], const float* __restrict__ bias,
                                    bf16* __restrict__ actH, bf16* __restrict__ actL,
                                    int lane, int row0, int col0)
{
    const int r4 = lane >> 2, cq = (lane & 3) * 2;
#pragma unroll
    for (int i = 0; i < 2; ++i)
#pragma unroll
        for (int j = 0; j < 2; ++j)
#pragma unroll
            for (int nb = 0; nb < 2; ++nb) {
                int cg = col0 + 16 * j + 8 * nb + cq;
                float2 bb = *(const float2*)(bias + cg);
                float* a = acc[i][j][nb];
                int rg = row0 + 16 * i + r4;
                float v0 = silu_f(a[0] + bb.x), v1 = silu_f(a[1] + bb.y);
                float v2 = silu_f(a[2] + bb.x), v3 = silu_f(a[3] + bb.y);
                __nv_bfloat162 h0 = __floats2bfloat162_rn(v0, v1);
                __nv_bfloat162 l0 = __floats2bfloat162_rn(v0 - __low2float(h0), v1 - __high2float(h0));
                __nv_bfloat162 h1 = __floats2bfloat162_rn(v2, v3);
                __nv_bfloat162 l1 = __floats2bfloat162_rn(v2 - __low2float(h1), v3 - __high2float(h1));
                *(__nv_bfloat162*)&actH[rg * PA + cg] = h0;
                *(__nv_bfloat162*)&actL[rg * PA + cg] = l0;
                *(__nv_bfloat162*)&actH[(rg + 8) * PA + cg] = h1;
                *(__nv_bfloat162*)&actL[(rg + 8) * PA + cg] = l1;
            }
}

#define ZERO_ACC(acc)                           \
    _Pragma("unroll")                           \
    for (int i = 0; i < 2; ++i)                 \
        _Pragma("unroll")                       \
        for (int j = 0; j < 2; ++j)             \
            _Pragma("unroll")                   \
            for (int nb = 0; nb < 2; ++nb)      \
                _Pragma("unroll")               \
                for (int e = 0; e < 4; ++e) acc[i][j][nb][e] = 0.0f;

// ---------------- WMMA bits (pre kernel only) ----------------
typedef wmma::fragment<wmma::matrix_a, 16, 16, 16, bf16, wmma::row_major> FragA;
typedef wmma::fragment<wmma::matrix_b, 16, 16, 16, bf16, wmma::row_major> FragB;
typedef wmma::fragment<wmma::accumulator, 16, 16, 16, float> FragC;

__device__ __forceinline__ void gemm_chunk(const bf16* aH, const bf16* aL,
                                           const bf16* bH, const bf16* bL,
                                           int ksteps, FragC (&acc)[2][2],
                                           int row0, int col0)
{
    for (int ks = 0; ks < ksteps; ++ks) {
        FragA faH[2], faL[2];
        FragB fbH[2], fbL[2];
#pragma unroll
        for (int i = 0; i < 2; ++i) {
            wmma::load_matrix_sync(faH[i], aH + (row0 + 16 * i) * PA + ks * 16, PA);
            wmma::load_matrix_sync(faL[i], aL + (row0 + 16 * i) * PA + ks * 16, PA);
        }
#pragma unroll
        for (int j = 0; j < 2; ++j) {
            wmma::load_matrix_sync(fbH[j], bH + (ks * 16) * PW + col0 + 16 * j, PW);
            wmma::load_matrix_sync(fbL[j], bL + (ks * 16) * PW + col0 + 16 * j, PW);
        }
#pragma unroll
        for (int i = 0; i < 2; ++i)
#pragma unroll
            for (int j = 0; j < 2; ++j) {
                wmma::mma_sync(acc[i][j], faH[i], fbH[j], acc[i][j]);
                wmma::mma_sync(acc[i][j], faH[i], fbL[j], acc[i][j]);
                wmma::mma_sync(acc[i][j], faL[i], fbH[j], acc[i][j]);
            }
    }
}

// ================= precompute: U[l] = ctx @ W1c[l] + te @ W1t[l] =================
__global__ __launch_bounds__(NT, 1)
void pre_ctxte(const float* __restrict__ ctx, const float* __restrict__ te)
{
    extern __shared__ char smem[];
    bf16* cH = (bf16*)(smem + PSM_CTX);
    bf16* cL = cH + ALO;
    bf16* tH = (bf16*)(smem + PSM_TE);
    bf16* tL = tH + ALO;
    bf16* wbA = (bf16*)(smem + PSM_WB);
    bf16* wbB = (bf16*)(smem + PSM_WB + WBUF_B);

    const int tid = threadIdx.x;
    const long long row0b = (long long)blockIdx.x * TB;

    const int w = tid >> 5;
    const int wr = w >> 2, wc = w & 3;
    const int row0 = wr * 32, col0 = wc * 32;

    {
        const float* sc = ctx + row0b * HHV;
        const float* st = te + row0b * HHV;
        for (int i = tid; i < 128 * 64; i += NT) {
            int r = i >> 6, c = (i & 63) * 2;
            float2 v = *(const float2*)&sc[r * HHV + c];
            split_store(cH + r * PA + c,     cL + r * PA + c,     v.x);
            split_store(cH + r * PA + c + 1, cL + r * PA + c + 1, v.y);
            float2 u = *(const float2*)&st[r * HHV + c];
            split_store(tH + r * PA + c,     tL + r * PA + c,     u.x);
            split_store(tH + r * PA + c + 1, tL + r * PA + c + 1, u.y);
        }
    }

    for (int l = 0; l < NL; ++l) {
        const bf16* wc_ = g_Wc + (size_t)l * E_C;
        const bf16* wt_ = g_Wt_ + (size_t)l * E_C;

        FragC acc[2][2];
#pragma unroll
        for (int i = 0; i < 2; ++i)
#pragma unroll
            for (int j = 0; j < 2; ++j) wmma::fill_fragment(acc[i][j], 0.0f);

        cpa(wbA, wc_, CB_MLP, tid);
        cpa(wbB, wc_ + CHW_ELEM, CB_MLP, tid);
        __pipeline_wait_prior(1); __syncthreads();
        gemm_chunk(cH, cL, wbA, wbA + 64 * PW, 4, acc, row0, col0);
        __syncthreads();
        cpa(wbA, wt_, CB_MLP, tid);
        __pipeline_wait_prior(1); __syncthreads();
        gemm_chunk(cH + 64, cL + 64, wbB, wbB + 64 * PW, 4, acc, row0, col0);
        __syncthreads();
        cpa(wbB, wt_ + CHW_ELEM, CB_MLP, tid);
        __pipeline_wait_prior(1); __syncthreads();
        gemm_chunk(tH, tL, wbA, wbA + 64 * PW, 4, acc, row0, col0);
        __pipeline_wait_prior(0); __syncthreads();
        gemm_chunk(tH + 64, tL + 64, wbB, wbB + 64 * PW, 4, acc, row0, col0);
        __syncthreads();

        float* Ubase = g_U + ((size_t)l * BATCH + row0b) * HHV;
#pragma unroll
        for (int i = 0; i < 2; ++i)
#pragma unroll
            for (int j = 0; j < 2; ++j)
                wmma::store_matrix_sync(Ubase + (size_t)(row0 + 16 * i) * HHV + col0 + 16 * j,
                                        acc[i][j], HHV, wmma::mem_row_major);
    }
}

// ================= flow kernel (raw mma.sync) =================
__global__ __launch_bounds__(NT, 1)
void biflow_mma(const float* __restrict__ x,
                const float* __restrict__ b1,
                const float* __restrict__ b2,
                const float* __restrict__ b3,
                const float* __restrict__ bs,
                const float* __restrict__ bt,
                const int*   __restrict__ perm,
                const int*   __restrict__ idx_a,
                const int*   __restrict__ idx_b,
                float* __restrict__ out)
{
    extern __shared__ char smem[];
    bf16*  actH  = (bf16*)(smem + SM_ACT);
    bf16*  actL  = actH + ALO;
    bf16*  wbA   = (bf16*)(smem + SM_WB);
    bf16*  wbB   = (bf16*)(smem + SM_WB + WBUF_B);
    float* cbufH = (float*)(smem + SM_CBH);
    float* zt    = (float*)(smem + SM_ZT);
    float* ldet  = (float*)(smem + SM_LDET);
    int* sa_s = (int*)(smem + SM_IDX);
    int* sb_s = sa_s + NL * ADIMV;
    int* da_s = sb_s + NL * ADIMV;
    int* db_s = da_s + NL * ADIMV;

    const int tid  = threadIdx.x;
    const int row0b = blockIdx.x * TB;

    // ---- init ----
    for (int idx = tid; idx < TB * DIMV; idx += NT) {
        int r = idx / DIMV, c = idx % DIMV;
        zt[r * ZP + c] = x[(long long)(row0b + r) * DIMV + c];
    }
    if (tid < TB) ldet[tid] = 0.0f;
    if (tid < NL * ADIMV) {
        int l = tid / ADIMV;
        int ia = idx_a[tid], ib = idx_b[tid];
        da_s[tid] = ia; db_s[tid] = ib;
        sa_s[tid] = perm[l * DIMV + ia];
        sb_s[tid] = perm[l * DIMV + ib];
    }
    __syncthreads();

    const int w = tid >> 5, lane = tid & 31;
    const int wr = w >> 2, wc = w & 3;
    const int row0 = wr * 32, col0 = wc * 32, col0h = wc * 16;
    const int r4 = lane >> 2, cq = (lane & 3) * 2;

    const uint32_t actHu = smem_u32(actH);
    const uint32_t dAL   = (uint32_t)(ALO * 2);
    const uint32_t wbAu  = smem_u32(wbA);
    const uint32_t wbBu  = smem_u32(wbB);

    for (int l = 0; l < NL; ++l) {
        const bf16* wza = g_Wza + (size_t)l * E_ZA;
        const bf16* w2  = g_W2 + (size_t)l * E_C;
        const bf16* w3  = g_W3 + (size_t)l * E_C;
        const bf16* whd = g_Whd + (size_t)l * E_HD;

        float acc[2][2][2][4];

        // ---- prefetch za + W2c0; load U into acc; build za act ----
        cpa(wbA, wza, CB_ZA, tid);                         // g0
        cpa(wbB, w2, CB_MLP, tid);                         // g1
        {
            const float* Ub = g_U + ((size_t)l * BATCH + row0b) * HHV;
#pragma unroll
            for (int i = 0; i < 2; ++i)
#pragma unroll
                for (int j = 0; j < 2; ++j)
#pragma unroll
                    for (int nb = 0; nb < 2; ++nb) {
                        int rg = row0 + 16 * i + r4;
                        int cg = col0 + 16 * j + 8 * nb + cq;
                        float2 u0 = *(const float2*)&Ub[(size_t)rg * HHV + cg];
                        float2 u1 = *(const float2*)&Ub[(size_t)(rg + 8) * HHV + cg];
                        acc[i][j][nb][0] = u0.x; acc[i][j][nb][1] = u0.y;
                        acc[i][j][nb][2] = u1.x; acc[i][j][nb][3] = u1.y;
                    }
        }
        for (int i = tid; i < 128 * 32; i += NT) {
            int r = i >> 5, k = i & 31;
            float v = (k < ADIMV) ? zt[r * ZP + sa_s[l * ADIMV + k]] : 0.0f;
            split_store(actH + r * PA + k, actL + r * PA + k, v);
        }
        __pipeline_wait_prior(1); __syncthreads();         // za(A) + act ready
        gemm32(actHu, dAL, wbAu, (uint32_t)(32 * PA * 2), 2, PA, acc, lane, row0, col0);
        __syncthreads();                                   // A free, act reads done
        cpa(wbA, w2 + CHW_ELEM, CB_MLP, tid);              // g2: W2c1
        epi(acc, b1 + l * HHV, actH, actL, lane, row0, col0);   // h1 -> act
        __syncthreads();

        // ---- GEMM2 ----
        ZERO_ACC(acc);
        __pipeline_wait_prior(1); __syncthreads();         // W2c0(B)
        gemm32(actHu, dAL, wbBu, (uint32_t)(64 * PW * 2), 4, PW, acc, lane, row0, col0);
        __syncthreads();                                   // B free
        cpa(wbB, w3, CB_MLP, tid);                         // g3: W3c0
        __pipeline_wait_prior(1); __syncthreads();         // W2c1(A)
        gemm32(actHu + 128, dAL, wbAu, (uint32_t)(64 * PW * 2), 4, PW, acc, lane, row0, col0);
        __syncthreads();                                   // A free, h1 reads done
        cpa(wbA, w3 + CHW_ELEM, CB_MLP, tid);              // g4: W3c1
        epi(acc, b2 + l * HHV, actH, actL, lane, row0, col0);   // h2 -> act
        __syncthreads();

        // ---- GEMM3 ----
        ZERO_ACC(acc);
        __pipeline_wait_prior(1); __syncthreads();         // W3c0(B)
        gemm32(actHu, dAL, wbBu, (uint32_t)(64 * PW * 2), 4, PW, acc, lane, row0, col0);
        __syncthreads();                                   // B free
        cpa(wbB, whd, CB_HD, tid);                         // g5: HDc0
        __pipeline_wait_prior(1); __syncthreads();         // W3c1(A)
        gemm32(actHu + 128, dAL, wbAu, (uint32_t)(64 * PW * 2), 4, PW, acc, lane, row0, col0);
        __syncthreads();                                   // A free, h2 reads done
        cpa(wbA, whd + CHH_ELEM, CB_HD, tid);              // g6: HDc1
        epi(acc, b3 + l * HHV, actH, actL, lane, row0, col0);   // h3 -> act
        __syncthreads();

        // ---- heads: C[128x40(padded 64)] = h3 @ [Ws|Wt|0] ----
        {
            float acc2[2][2][4];
#pragma unroll
            for (int i = 0; i < 2; ++i)
#pragma unroll
                for (int nb = 0; nb < 2; ++nb)
#pragma unroll
                    for (int e = 0; e < 4; ++e) acc2[i][nb][e] = 0.0f;

            const int arow = lane & 15, akk = (lane >> 4) * 8;
            const int bkr = (lane & 7) + ((lane >> 3) & 1) * 8, bnc = (lane >> 4) * 8;

            __pipeline_wait_prior(1); __syncthreads();     // HDc0(B)
            for (int q = 0; q < 2; ++q) {
                uint32_t wbu = (q == 0) ? wbBu : wbAu;
                for (int ks = 0; ks < 4; ++ks) {
                    uint32_t aF[2][2][4], bFh[4], bFl[4];
#pragma unroll
                    for (int i = 0; i < 2; ++i) {
                        uint32_t ad = actHu + (uint32_t)(((row0 + 16 * i + arow) * PA
                                        + q * 64 + ks * 16 + akk) * 2);
                        ldm4(aF[0][i], ad);
                        ldm4(aF[1][i], ad + dAL);
                    }
                    uint32_t bd = wbu + (uint32_t)(((ks * 16 + bkr) * PH + col0h + bnc) * 2);
                    ldm4t(bFh, bd);
                    ldm4t(bFl, bd + (uint32_t)(64 * PH * 2));
#pragma unroll
                    for (int i = 0; i < 2; ++i)
#pragma unroll
                        for (int nb = 0; nb < 2; ++nb) {
                            mmab(acc2[i][nb], aF[0][i], &bFh[2 * nb]);
                            mmab(acc2[i][nb], aF[0][i], &bFl[2 * nb]);
                            mmab(acc2[i][nb], aF[1][i], &bFh[2 * nb]);
                        }
                }
                if (q == 0) { __pipeline_wait_prior(0); __syncthreads(); }  // HDc1(A)
            }
            // store head acc to cbufH (f32)
#pragma unroll
            for (int i = 0; i < 2; ++i)
#pragma unroll
                for (int nb = 0; nb < 2; ++nb) {
                    int rg = row0 + 16 * i + r4;
                    int cg = col0h + 8 * nb + cq;
                    *(float2*)&cbufH[rg * PCH + cg] = make_float2(acc2[i][nb][0], acc2[i][nb][1]);
                    *(float2*)&cbufH[(rg + 8) * PCH + cg] = make_float2(acc2[i][nb][2], acc2[i][nb][3]);
                }
            __syncthreads();
        }

        // ---- coupling: 128 threads, each owns one row ----
        if (tid < 128) {
            float sv[ADIMV], tv[ADIMV];
#pragma unroll
            for (int j = 0; j < ADIMV; ++j) {
                float s = cbufH[tid * PCH + j] + bs[l * ADIMV + j];
                sv[j] = fminf(fmaxf(s, -CLIPV), CLIPV);
                tv[j] = cbufH[tid * PCH + ADIMV + j] + bt[l * ADIMV + j];
            }
            float zan[ADIMV], ybn[ADIMV], lsum = 0.0f;
#pragma unroll
            for (int j = 0; j < ADIMV; ++j) {
                float zb = zt[tid * ZP + sb_s[l * ADIMV + j]];
                ybn[j] = fmaf(zb, __expf(sv[j]), tv[j]);
                zan[j] = zt[tid * ZP + sa_s[l * ADIMV + j]];
                lsum += sv[j];
            }
#pragma unroll
            for (int j = 0; j < ADIMV; ++j) {
                zt[tid * ZP + da_s[l * ADIMV + j]] = zan[j];
                zt[tid * ZP + db_s[l * ADIMV + j]] = ybn[j];
            }
            ldet[tid] += lsum;
        }
        __syncthreads();
    }

    // ---- output: z (B x 40) then logdet (B) ----
    for (int idx = tid; idx < TB * DIMV; idx += NT) {
        int r = idx / DIMV, c = idx % DIMV;
        out[(long long)(row0b + r) * DIMV + c] = zt[r * ZP + c];
    }
    if (tid < TB)
        out[(long long)BATCH * DIMV + row0b + tid] = ldet[tid];
}

extern "C" void kernel_launch(void* const* d_in, const int* in_sizes, int n_in,
                              void* d_out, int out_size) {
    const float* x    = (const float*)d_in[0];
    const float* ctx  = (const float*)d_in[1];
    const float* te   = (const float*)d_in[2];
    const float* W1   = (const float*)d_in[3];
    const float* b1   = (const float*)d_in[4];
    const float* W2   = (const float*)d_in[5];
    const float* b2   = (const float*)d_in[6];
    const float* W3   = (const float*)d_in[7];
    const float* b3   = (const float*)d_in[8];
    const float* Ws   = (const float*)d_in[9];
    const float* bs   = (const float*)d_in[10];
    const float* Wt   = (const float*)d_in[11];
    const float* bt   = (const float*)d_in[12];
    const int*   perm = (const int*)d_in[13];
    const int*   ia   = (const int*)d_in[14];
    const int*   ib   = (const int*)d_in[15];
    float* out = (float*)d_out;

    prep_weights<<<512, 256>>>(W1, W2, W3, Ws, Wt);

    cudaFuncSetAttribute(pre_ctxte,
                         cudaFuncAttributeMaxDynamicSharedMemorySize, SMEM_PRE);
    pre_ctxte<<<BATCH / TB, NT, SMEM_PRE>>>(ctx, te);

    cudaFuncSetAttribute(biflow_mma,
                         cudaFuncAttributeMaxDynamicSharedMemorySize, SMEM_TOTAL);
    biflow_mma<<<BATCH / TB, NT, SMEM_TOTAL>>>(
        x, b1, b2, b3, bs, bt, perm, ia, ib, out);
}

// round 16
// speedup vs baseline: 1.2779x; 1.2779x over previous
#include <cuda_runtime.h>
#include <cuda_bf16.h>
#include <cuda_pipeline.h>
#include <mma.h>
#include <cstdint>

using namespace nvcuda;

// Problem constants
#define NL    6
#define DIMV  40
#define ADIMV 20
#define HHV   128
#define DINV  276
#define BATCH 131072
#define CLIPV 2.0f

#define TB 128
#define NT 512
#define ZP 44

// pitches
#define PA 136      // activation tile pitch (bf16 elems)
#define PW 136      // weight tile pitch (bf16 elems)
#define PC 132      // C staging pitch (f32 elems)
#define PCH 68      // heads C staging pitch (f32)
#define PH 72       // heads weight pitch (bf16)

#define ALO (128*PA)        // act lo-tile element offset

// weight image element counts per layer
#define E_ZA  (2*32*PA)     // 8704   (hi32|lo32)
#define E_C   (2*128*PW)    // 34816  (2 chunks of [hi64|lo64])
#define E_HD  (2*128*PH)    // 18432  (2 chunks of [hi64|lo64])

// chunk sizes
#define CHW_ELEM (128*PW)
#define CHH_ELEM (128*PH)
#define CB_MLP (CHW_ELEM*2)
#define CB_ZA  (E_ZA*2)
#define CB_HD  (CHH_ELEM*2)

#define WBUF_B 34816

// ---- flow kernel SMEM layout (bytes) ----
#define SM_ACT  0
#define SM_WB   (2*128*PA*2)                  // 69632
#define SM_CB   (SM_WB + 2*WBUF_B)            // 139264
#define SM_ZT   (SM_CB + 128*PC*4)            // 206848
#define SM_LDET (SM_ZT + TB*ZP*4)             // 229376
#define SM_IDX  (SM_LDET + TB*4)              // 229888
#define SMEM_TOTAL (SM_IDX + 4*NL*ADIMV*4)    // 231808

// ---- pre kernel SMEM layout ----
#define PSM_CTX 0
#define PSM_TE  (2*128*PA*2)
#define PSM_WB  (2*2*128*PA*2)
#define SMEM_PRE (PSM_WB + 2*WBUF_B)          // 208896

typedef __nv_bfloat16 bf16;

__device__ __align__(16) bf16 g_Wza[NL * E_ZA];
__device__ __align__(16) bf16 g_Wc [NL * E_C];
__device__ __align__(16) bf16 g_Wt_[NL * E_C];
__device__ __align__(16) bf16 g_W2 [NL * E_C];
__device__ __align__(16) bf16 g_W3 [NL * E_C];
__device__ __align__(16) bf16 g_Whd[NL * E_HD];

__device__ float g_U[(size_t)NL * BATCH * HHV];

__device__ __forceinline__ void split_store(bf16* hi_p, bf16* lo_p, float v) {
    bf16 h = __float2bfloat16(v);
    bf16 lo = __float2bfloat16(v - __bfloat162float(h));
    *hi_p = h; *lo_p = lo;
}

__global__ void prep_weights(const float* __restrict__ W1,
                             const float* __restrict__ W2,
                             const float* __restrict__ W3,
                             const float* __restrict__ Ws,
                             const float* __restrict__ Wt)
{
    int stride = gridDim.x * blockDim.x;
    int tid0 = blockIdx.x * blockDim.x + threadIdx.x;

    for (int t = tid0; t < NL * 32 * PA; t += stride) {
        int c = t % PA, k = (t / PA) % 32, l = t / (PA * 32);
        float v = (k < ADIMV && c < HHV) ? W1[((long long)l * DINV + k) * HHV + c] : 0.0f;
        bf16* base = g_Wza + (size_t)l * E_ZA;
        split_store(base + k * PA + c, base + 32 * PA + k * PA + c, v);
    }
    for (int t = tid0; t < NL * 128 * PW; t += stride) {
        int c = t % PW, k = (t / PW) % 128, l = t / (PW * 128);
        float vc = 0.f, vt = 0.f, v2 = 0.f, v3 = 0.f;
        if (c < HHV) {
            vc = W1[((long long)l * DINV + ADIMV + k) * HHV + c];
            vt = W1[((long long)l * DINV + ADIMV + HHV + k) * HHV + c];
            v2 = W2[((long long)l * HHV + k) * HHV + c];
            v3 = W3[((long long)l * HHV + k) * HHV + c];
        }
        int chunk = k >> 6, kr = k & 63;
        size_t o_hi = (size_t)l * E_C + (size_t)chunk * CHW_ELEM + (size_t)kr * PW + c;
        size_t o_lo = o_hi + (size_t)64 * PW;
        split_store(g_Wc + o_hi,  g_Wc + o_lo,  vc);
        split_store(g_Wt_ + o_hi, g_Wt_ + o_lo, vt);
        split_store(g_W2 + o_hi,  g_W2 + o_lo,  v2);
        split_store(g_W3 + o_hi,  g_W3 + o_lo,  v3);
    }
    for (int t = tid0; t < NL * 128 * PH; t += stride) {
        int c = t % PH, k = (t / PH) % 128, l = t / (PH * 128);
        float v = 0.0f;
        if (c < ADIMV)           v = Ws[((long long)l * HHV + k) * ADIMV + c];
        else if (c < 2 * ADIMV)  v = Wt[((long long)l * HHV + k) * ADIMV + (c - ADIMV)];
        int chunk = k >> 6, kr = k & 63;
        size_t o_hi = (size_t)l * E_HD + (size_t)chunk * CHH_ELEM + (size_t)kr * PH + c;
        split_store(g_Whd + o_hi, g_Whd + o_hi + 64 * PH, v);
    }
}

__device__ __forceinline__ float silu_f(float v) { return v / (1.0f + __expf(-v)); }

__device__ __forceinline__ void cpa(void* dst, const void* src, int bytes, int tid) {
    char* d = (char*)dst;
    const char* s = (const char*)src;
    for (int i = tid * 16; i < bytes; i += NT * 16)
        __pipeline_memcpy_async(d + i, s + i, 16);
    __pipeline_commit();
}

typedef wmma::fragment<wmma::matrix_a, 16, 16, 16, bf16, wmma::row_major> FragA;
typedef wmma::fragment<wmma::matrix_b, 16, 16, 16, bf16, wmma::row_major> FragB;
typedef wmma::fragment<wmma::accumulator, 16, 16, 16, float> FragC;

// 3-term split MMA: acc[2][2] covers rows row0..+31, cols col0..+31.
__device__ __forceinline__ void gemm_chunk(const bf16* aH, const bf16* aL,
                                           const bf16* bH, const bf16* bL,
                                           int ksteps, FragC (&acc)[2][2],
                                           int row0, int col0)
{
    for (int ks = 0; ks < ksteps; ++ks) {
        FragA faH[2], faL[2];
        FragB fbH[2], fbL[2];
#pragma unroll
        for (int i = 0; i < 2; ++i) {
            wmma::load_matrix_sync(faH[i], aH + (row0 + 16 * i) * PA + ks * 16, PA);
            wmma::load_matrix_sync(faL[i], aL + (row0 + 16 * i) * PA + ks * 16, PA);
        }
#pragma unroll
        for (int j = 0; j < 2; ++j) {
            wmma::load_matrix_sync(fbH[j], bH + (ks * 16) * PW + col0 + 16 * j, PW);
            wmma::load_matrix_sync(fbL[j], bL + (ks * 16) * PW + col0 + 16 * j, PW);
        }
#pragma unroll
        for (int i = 0; i < 2; ++i)
#pragma unroll
            for (int j = 0; j < 2; ++j) {
                wmma::mma_sync(acc[i][j], faH[i], fbH[j], acc[i][j]);
                wmma::mma_sync(acc[i][j], faH[i], fbL[j], acc[i][j]);
                wmma::mma_sync(acc[i][j], faL[i], fbH[j], acc[i][j]);
            }
    }
}

// warp-local epilogue: store acc to this warp's private cbuf patch, then each
// lane processes one row of the 32x32 patch (bias+silu+hi/lo split -> act).
// No block barrier: patch is written and read by the SAME warp only.
__device__ __forceinline__ void epi_warp(FragC (&acc)[2][2], float* __restrict__ cbuf,
                                         const float* __restrict__ bias,
                                         bf16* __restrict__ actH, bf16* __restrict__ actL,
                                         int lane, int row0, int col0)
{
#pragma unroll
    for (int i = 0; i < 2; ++i)
#pragma unroll
        for (int j = 0; j < 2; ++j)
            wmma::store_matrix_sync(cbuf + (row0 + 16 * i) * PC + col0 + 16 * j,
                                    acc[i][j], PC, wmma::mem_row_major);
    __syncwarp();
    const int r = row0 + lane;
    const float* crow = cbuf + r * PC;
#pragma unroll
    for (int c4 = 0; c4 < 32; c4 += 4) {
        int c = col0 + c4;
        float4 v = *(const float4*)&crow[c];
        float s0 = silu_f(v.x + bias[c]);
        float s1 = silu_f(v.y + bias[c + 1]);
        float s2 = silu_f(v.z + bias[c + 2]);
        float s3 = silu_f(v.w + bias[c + 3]);
        __nv_bfloat162 h0 = __floats2bfloat162_rn(s0, s1);
        __nv_bfloat162 l0 = __floats2bfloat162_rn(s0 - __low2float(h0), s1 - __high2float(h0));
        __nv_bfloat162 h1 = __floats2bfloat162_rn(s2, s3);
        __nv_bfloat162 l1 = __floats2bfloat162_rn(s2 - __low2float(h1), s3 - __high2float(h1));
        uint2 hv, lv;
        hv.x = *(uint32_t*)&h0; hv.y = *(uint32_t*)&h1;
        lv.x = *(uint32_t*)&l0; lv.y = *(uint32_t*)&l1;
        *(uint2*)&actH[r * PA + c] = hv;
        *(uint2*)&actL[r * PA + c] = lv;
    }
}

// ================= precompute: U[l] = ctx @ W1c[l] + te @ W1t[l] =================
__global__ __launch_bounds__(NT, 1)
void pre_ctxte(const float* __restrict__ ctx, const float* __restrict__ te)
{
    extern __shared__ char smem[];
    bf16* cH = (bf16*)(smem + PSM_CTX);
    bf16* cL = cH + ALO;
    bf16* tH = (bf16*)(smem + PSM_TE);
    bf16* tL = tH + ALO;
    bf16* wbA = (bf16*)(smem + PSM_WB);
    bf16* wbB = (bf16*)(smem + PSM_WB + WBUF_B);

    const int tid = threadIdx.x;
    const long long row0b = (long long)blockIdx.x * TB;

    const int w = tid >> 5;
    const int wr = w >> 2, wc = w & 3;
    const int row0 = wr * 32, col0 = wc * 32;

    {
        const float* sc = ctx + row0b * HHV;
        const float* st = te + row0b * HHV;
        for (int i = tid; i < 128 * 64; i += NT) {
            int r = i >> 6, c = (i & 63) * 2;
            float2 v = *(const float2*)&sc[r * HHV + c];
            split_store(cH + r * PA + c,     cL + r * PA + c,     v.x);
            split_store(cH + r * PA + c + 1, cL + r * PA + c + 1, v.y);
            float2 u = *(const float2*)&st[r * HHV + c];
            split_store(tH + r * PA + c,     tL + r * PA + c,     u.x);
            split_store(tH + r * PA + c + 1, tL + r * PA + c + 1, u.y);
        }
    }

    for (int l = 0; l < NL; ++l) {
        const bf16* wc_ = g_Wc + (size_t)l * E_C;
        const bf16* wt_ = g_Wt_ + (size_t)l * E_C;

        FragC acc[2][2];
#pragma unroll
        for (int i = 0; i < 2; ++i)
#pragma unroll
            for (int j = 0; j < 2; ++j) wmma::fill_fragment(acc[i][j], 0.0f);

        cpa(wbA, wc_, CB_MLP, tid);
        cpa(wbB, wc_ + CHW_ELEM, CB_MLP, tid);
        __pipeline_wait_prior(1); __syncthreads();
        gemm_chunk(cH, cL, wbA, wbA + 64 * PW, 4, acc, row0, col0);
        __syncthreads();
        cpa(wbA, wt_, CB_MLP, tid);
        __pipeline_wait_prior(1); __syncthreads();
        gemm_chunk(cH + 64, cL + 64, wbB, wbB + 64 * PW, 4, acc, row0, col0);
        __syncthreads();
        cpa(wbB, wt_ + CHW_ELEM, CB_MLP, tid);
        __pipeline_wait_prior(1); __syncthreads();
        gemm_chunk(tH, tL, wbA, wbA + 64 * PW, 4, acc, row0, col0);
        __pipeline_wait_prior(0); __syncthreads();
        gemm_chunk(tH + 64, tL + 64, wbB, wbB + 64 * PW, 4, acc, row0, col0);
        __syncthreads();

        float* Ubase = g_U + ((size_t)l * BATCH + row0b) * HHV;
#pragma unroll
        for (int i = 0; i < 2; ++i)
#pragma unroll
            for (int j = 0; j < 2; ++j)
                wmma::store_matrix_sync(Ubase + (size_t)(row0 + 16 * i) * HHV + col0 + 16 * j,
                                        acc[i][j], HHV, wmma::mem_row_major);
    }
}

// ================= flow kernel =================
__global__ __launch_bounds__(NT, 1)
void biflow_wmma(const float* __restrict__ x,
                 const float* __restrict__ b1,
                 const float* __restrict__ b2,
                 const float* __restrict__ b3,
                 const float* __restrict__ bs,
                 const float* __restrict__ bt,
                 const int*   __restrict__ perm,
                 const int*   __restrict__ idx_a,
                 const int*   __restrict__ idx_b,
                 float* __restrict__ out)
{
    extern __shared__ char smem[];
    bf16*  actH = (bf16*)(smem + SM_ACT);
    bf16*  actL = actH + ALO;
    bf16*  wbA  = (bf16*)(smem + SM_WB);
    bf16*  wbB  = (bf16*)(smem + SM_WB + WBUF_B);
    float* cbuf = (float*)(smem + SM_CB);
    float* zt   = (float*)(smem + SM_ZT);
    float* ldet = (float*)(smem + SM_LDET);
    int* sa_s = (int*)(smem + SM_IDX);
    int* sb_s = sa_s + NL * ADIMV;
    int* da_s = sb_s + NL * ADIMV;
    int* db_s = da_s + NL * ADIMV;

    const int tid  = threadIdx.x;
    const int row0b = blockIdx.x * TB;

    // ---- init ----
    for (int idx = tid; idx < TB * DIMV; idx += NT) {
        int r = idx / DIMV, c = idx % DIMV;
        zt[r * ZP + c] = x[(long long)(row0b + r) * DIMV + c];
    }
    if (tid < TB) ldet[tid] = 0.0f;
    if (tid < NL * ADIMV) {
        int l = tid / ADIMV;
        int ia = idx_a[tid], ib = idx_b[tid];
        da_s[tid] = ia; db_s[tid] = ib;
        sa_s[tid] = perm[l * DIMV + ia];
        sb_s[tid] = perm[l * DIMV + ib];
    }
    __syncthreads();

    const int w = tid >> 5, lane = tid & 31;
    const int wr = w >> 2, wc = w & 3;
    const int row0 = wr * 32, col0 = wc * 32, col0h = wc * 16;

    for (int l = 0; l < NL; ++l) {
        const bf16* wza = g_Wza + (size_t)l * E_ZA;
        const bf16* w2  = g_W2 + (size_t)l * E_C;
        const bf16* w3  = g_W3 + (size_t)l * E_C;
        const bf16* whd = g_Whd + (size_t)l * E_HD;

        FragC acc[2][2];

        // ---- prefetch za + W2c0; meanwhile build za act and load U ----
        cpa(wbA, wza, CB_ZA, tid);               // g0
        cpa(wbB, w2, CB_MLP, tid);               // g1
        {
            const float* Ubase = g_U + ((size_t)l * BATCH + row0b) * HHV;
#pragma unroll
            for (int i = 0; i < 2; ++i)
#pragma unroll
                for (int j = 0; j < 2; ++j)
                    wmma::load_matrix_sync(acc[i][j],
                        Ubase + (size_t)(row0 + 16 * i) * HHV + col0 + 16 * j,
                        HHV, wmma::mem_row_major);
        }
        for (int i = tid; i < 128 * 32; i += NT) {
            int r = i >> 5, k = i & 31;
            float v = (k < ADIMV) ? zt[r * ZP + sa_s[l * ADIMV + k]] : 0.0f;
            split_store(actH + r * PA + k, actL + r * PA + k, v);
        }
        __pipeline_wait_prior(1); __syncthreads();         // za(A) + act ready
        gemm_chunk(actH, actL, wbA, wbA + 32 * PA, 2, acc, row0, col0);
        __syncthreads();                                   // A free, act reads done
        cpa(wbA, w2 + CHW_ELEM, CB_MLP, tid);              // g2: W2c1
        epi_warp(acc, cbuf, b1 + l * HHV, actH, actL, lane, row0, col0);  // h1 -> act

        // ---- GEMM2 ----
#pragma unroll
        for (int i = 0; i < 2; ++i)
#pragma unroll
            for (int j = 0; j < 2; ++j) wmma::fill_fragment(acc[i][j], 0.0f);
        __pipeline_wait_prior(1); __syncthreads();         // W2c0(B) + h1 act complete
        gemm_chunk(actH, actL, wbB, wbB + 64 * PW, 4, acc, row0, col0);
        __syncthreads();                                   // B free
        cpa(wbB, w3, CB_MLP, tid);                         // g3: W3c0
        __pipeline_wait_prior(1); __syncthreads();         // W2c1(A)
        gemm_chunk(actH + 64, actL + 64, wbA, wbA + 64 * PW, 4, acc, row0, col0);
        __syncthreads();                                   // A free, h1 reads done
        cpa(wbA, w3 + CHW_ELEM, CB_MLP, tid);              // g4: W3c1
        epi_warp(acc, cbuf, b2 + l * HHV, actH, actL, lane, row0, col0);  // h2 -> act

        // ---- GEMM3 ----
#pragma unroll
        for (int i = 0; i < 2; ++i)
#pragma unroll
            for (int j = 0; j < 2; ++j) wmma::fill_fragment(acc[i][j], 0.0f);
        __pipeline_wait_prior(1); __syncthreads();         // W3c0(B) + h2 act complete
        gemm_chunk(actH, actL, wbB, wbB + 64 * PW, 4, acc, row0, col0);
        __syncthreads();                                   // B free
        cpa(wbB, whd, CB_HD, tid);                         // g5: HDc0
        __pipeline_wait_prior(1); __syncthreads();         // W3c1(A)
        gemm_chunk(actH + 64, actL + 64, wbA, wbA + 64 * PW, 4, acc, row0, col0);
        __syncthreads();                                   // A free, h2 reads done
        cpa(wbA, whd + CHH_ELEM, CB_HD, tid);              // g6: HDc1
        epi_warp(acc, cbuf, b3 + l * HHV, actH, actL, lane, row0, col0);  // h3 -> act

        // ---- heads ----
        {
            FragC acc2[2];
            wmma::fill_fragment(acc2[0], 0.0f);
            wmma::fill_fragment(acc2[1], 0.0f);
            __pipeline_wait_prior(1); __syncthreads();     // HDc0(B) + h3 act complete
            for (int q = 0; q < 2; ++q) {
                const bf16* bH = (q == 0) ? wbB : wbA;
                const bf16* bL = bH + 64 * PH;
                const bf16* aHq = actH + q * 64;
                const bf16* aLq = actL + q * 64;
                for (int ks = 0; ks < 4; ++ks) {
                    FragA faH[2], faL[2];
                    FragB fbH, fbL;
#pragma unroll
                    for (int i = 0; i < 2; ++i) {
                        wmma::load_matrix_sync(faH[i], aHq + (row0 + 16 * i) * PA + ks * 16, PA);
                        wmma::load_matrix_sync(faL[i], aLq + (row0 + 16 * i) * PA + ks * 16, PA);
                    }
                    wmma::load_matrix_sync(fbH, bH + (ks * 16) * PH + col0h, PH);
                    wmma::load_matrix_sync(fbL, bL + (ks * 16) * PH + col0h, PH);
#pragma unroll
                    for (int i = 0; i < 2; ++i) {
                        wmma::mma_sync(acc2[i], faH[i], fbH, acc2[i]);
                        wmma::mma_sync(acc2[i], faH[i], fbL, acc2[i]);
                        wmma::mma_sync(acc2[i], faL[i], fbH, acc2[i]);
                    }
                }
                if (q == 0) { __pipeline_wait_prior(0); __syncthreads(); }  // HDc1(A)
            }
            __syncthreads();
#pragma unroll
            for (int i = 0; i < 2; ++i)
                wmma::store_matrix_sync(cbuf + (row0 + 16 * i) * PCH + col0h,
                                        acc2[i], PCH, wmma::mem_row_major);
            __syncthreads();
        }

        // ---- coupling: 128 threads, each owns one row ----
        if (tid < 128) {
            float sv[ADIMV], tv[ADIMV];
#pragma unroll
            for (int j = 0; j < ADIMV; ++j) {
                float s = cbuf[tid * PCH + j] + bs[l * ADIMV + j];
                sv[j] = fminf(fmaxf(s, -CLIPV), CLIPV);
                tv[j] = cbuf[tid * PCH + ADIMV + j] + bt[l * ADIMV + j];
            }
            float zan[ADIMV], ybn[ADIMV], lsum = 0.0f;
#pragma unroll
            for (int j = 0; j < ADIMV; ++j) {
                float zb = zt[tid * ZP + sb_s[l * ADIMV + j]];
                ybn[j] = fmaf(zb, __expf(sv[j]), tv[j]);
                zan[j] = zt[tid * ZP + sa_s[l * ADIMV + j]];
                lsum += sv[j];
            }
#pragma unroll
            for (int j = 0; j < ADIMV; ++j) {
                zt[tid * ZP + da_s[l * ADIMV + j]] = zan[j];
                zt[tid * ZP + db_s[l * ADIMV + j]] = ybn[j];
            }
            ldet[tid] += lsum;
        }
        __syncthreads();
    }

    // ---- output: z (B x 40) then logdet (B) ----
    for (int idx = tid; idx < TB * DIMV; idx += NT) {
        int r = idx / DIMV, c = idx % DIMV;
        out[(long long)(row0b + r) * DIMV + c] = zt[r * ZP + c];
    }
    if (tid < TB)
        out[(long long)BATCH * DIMV + row0b + tid] = ldet[tid];
}

extern "C" void kernel_launch(void* const* d_in, const int* in_sizes, int n_in,
                              void* d_out, int out_size) {
    const float* x    = (const float*)d_in[0];
    const float* ctx  = (const float*)d_in[1];
    const float* te   = (const float*)d_in[2];
    const float* W1   = (const float*)d_in[3];
    const float* b1   = (const float*)d_in[4];
    const float* W2   = (const float*)d_in[5];
    const float* b2   = (const float*)d_in[6];
    const float* W3   = (const float*)d_in[7];
    const float* b3   = (const float*)d_in[8];
    const float* Ws   = (const float*)d_in[9];
    const float* bs   = (const float*)d_in[10];
    const float* Wt   = (const float*)d_in[11];
    const float* bt   = (const float*)d_in[12];
    const int*   perm = (const int*)d_in[13];
    const int*   ia   = (const int*)d_in[14];
    const int*   ib   = (const int*)d_in[15];
    float* out = (float*)d_out;

    prep_weights<<<512, 256>>>(W1, W2, W3, Ws, Wt);

    cudaFuncSetAttribute(pre_ctxte,
                         cudaFuncAttributeMaxDynamicSharedMemorySize, SMEM_PRE);
    pre_ctxte<<<BATCH / TB, NT, SMEM_PRE>>>(ctx, te);

    cudaFuncSetAttribute(biflow_wmma,
                         cudaFuncAttributeMaxDynamicSharedMemorySize, SMEM_TOTAL);
    biflow_wmma<<<BATCH / TB, NT, SMEM_TOTAL>>>(
        x, b1, b2, b3, bs, bt, perm, ia, ib, out);
}

// round 17
// speedup vs baseline: 1.3138x; 1.0280x over previous
#include <cuda_runtime.h>
#include <cuda_bf16.h>
#include <cuda_pipeline.h>
#include <mma.h>
#include <cstdint>

using namespace nvcuda;

// Problem constants
#define NL    6
#define DIMV  40
#define ADIMV 20
#define HHV   128
#define DINV  276
#define BATCH 131072
#define CLIPV 2.0f

// flow tiling: 64-row tiles, 8 warps, 2 blocks/SM
#define TB 64
#define NT 256
#define ZP 41

// pre tiling (unchanged)
#define TBP 128
#define NTP 512

// pitches
#define PA 136      // activation tile pitch (bf16 elems)
#define PW 136      // weight tile pitch (bf16 elems)
#define PC 132      // C staging pitch (f32 elems)
#define PCH 68      // heads C staging pitch (f32)
#define PH 72       // heads weight pitch (bf16)

#define ALO_F (TB*PA)       // flow act lo-tile element offset
#define ALO_P (TBP*PA)      // pre act lo-tile element offset

// weight image element counts per layer
#define E_ZA  (2*32*PA)     // 8704   (hi32|lo32)
#define E_C   (2*128*PW)    // 34816  (2 chunks of [hi64|lo64])
#define E_HD  (2*128*PH)    // 18432  (2 chunks of [hi64|lo64])

// chunk sizes (bytes)
#define CHW_ELEM (128*PW)
#define CHH_ELEM (128*PH)
#define CB_MLP (CHW_ELEM*2)   // 34816
#define CB_ZA  (E_ZA*2)       // 17408
#define CB_HD  (CHH_ELEM*2)   // 18432

#define WBUF_B 34816          // single weight buffer

// ---- flow kernel SMEM layout (bytes) ----
#define SM_ACT  0
#define SM_WB   (2*TB*PA*2)                   // 34816
#define SM_CB   (SM_WB + WBUF_B)              // 69632
#define SM_ZT   (SM_CB + TB*PC*4)             // 103424
#define SM_LDET (SM_ZT + TB*ZP*4)             // 113920
#define SM_IDX  (SM_LDET + TB*4)              // 114176
#define SMEM_TOTAL (SM_IDX + 4*NL*ADIMV*2)    // 115136  (x2 = 230272 <= 228KB/SM)

// ---- pre kernel SMEM layout ----
#define PSM_CTX 0
#define PSM_TE  (2*TBP*PA*2)
#define PSM_WB  (2*2*TBP*PA*2)
#define SMEM_PRE (PSM_WB + 2*WBUF_B)          // 208896

typedef __nv_bfloat16 bf16;

__device__ __align__(16) bf16 g_Wza[NL * E_ZA];
__device__ __align__(16) bf16 g_Wc [NL * E_C];
__device__ __align__(16) bf16 g_Wt_[NL * E_C];
__device__ __align__(16) bf16 g_W2 [NL * E_C];
__device__ __align__(16) bf16 g_W3 [NL * E_C];
__device__ __align__(16) bf16 g_Whd[NL * E_HD];

__device__ float g_U[(size_t)NL * BATCH * HHV];

__device__ __forceinline__ void split_store(bf16* hi_p, bf16* lo_p, float v) {
    bf16 h = __float2bfloat16(v);
    bf16 lo = __float2bfloat16(v - __bfloat162float(h));
    *hi_p = h; *lo_p = lo;
}

__global__ void prep_weights(const float* __restrict__ W1,
                             const float* __restrict__ W2,
                             const float* __restrict__ W3,
                             const float* __restrict__ Ws,
                             const float* __restrict__ Wt)
{
    int stride = gridDim.x * blockDim.x;
    int tid0 = blockIdx.x * blockDim.x + threadIdx.x;

    for (int t = tid0; t < NL * 32 * PA; t += stride) {
        int c = t % PA, k = (t / PA) % 32, l = t / (PA * 32);
        float v = (k < ADIMV && c < HHV) ? W1[((long long)l * DINV + k) * HHV + c] : 0.0f;
        bf16* base = g_Wza + (size_t)l * E_ZA;
        split_store(base + k * PA + c, base + 32 * PA + k * PA + c, v);
    }
    for (int t = tid0; t < NL * 128 * PW; t += stride) {
        int c = t % PW, k = (t / PW) % 128, l = t / (PW * 128);
        float vc = 0.f, vt = 0.f, v2 = 0.f, v3 = 0.f;
        if (c < HHV) {
            vc = W1[((long long)l * DINV + ADIMV + k) * HHV + c];
            vt = W1[((long long)l * DINV + ADIMV + HHV + k) * HHV + c];
            v2 = W2[((long long)l * HHV + k) * HHV + c];
            v3 = W3[((long long)l * HHV + k) * HHV + c];
        }
        int chunk = k >> 6, kr = k & 63;
        size_t o_hi = (size_t)l * E_C + (size_t)chunk * CHW_ELEM + (size_t)kr * PW + c;
        size_t o_lo = o_hi + (size_t)64 * PW;
        split_store(g_Wc + o_hi,  g_Wc + o_lo,  vc);
        split_store(g_Wt_ + o_hi, g_Wt_ + o_lo, vt);
        split_store(g_W2 + o_hi,  g_W2 + o_lo,  v2);
        split_store(g_W3 + o_hi,  g_W3 + o_lo,  v3);
    }
    for (int t = tid0; t < NL * 128 * PH; t += stride) {
        int c = t % PH, k = (t / PH) % 128, l = t / (PH * 128);
        float v = 0.0f;
        if (c < ADIMV)           v = Ws[((long long)l * HHV + k) * ADIMV + c];
        else if (c < 2 * ADIMV)  v = Wt[((long long)l * HHV + k) * ADIMV + (c - ADIMV)];
        int chunk = k >> 6, kr = k & 63;
        size_t o_hi = (size_t)l * E_HD + (size_t)chunk * CHH_ELEM + (size_t)kr * PH + c;
        split_store(g_Whd + o_hi, g_Whd + o_hi + 64 * PH, v);
    }
}

__device__ __forceinline__ float silu_f(float v) { return v / (1.0f + __expf(-v)); }

__device__ __forceinline__ void cpa(void* dst, const void* src, int bytes, int tid, int nt) {
    char* d = (char*)dst;
    const char* s = (const char*)src;
    for (int i = tid * 16; i < bytes; i += nt * 16)
        __pipeline_memcpy_async(d + i, s + i, 16);
    __pipeline_commit();
}

typedef wmma::fragment<wmma::matrix_a, 16, 16, 16, bf16, wmma::row_major> FragA;
typedef wmma::fragment<wmma::matrix_b, 16, 16, 16, bf16, wmma::row_major> FragB;
typedef wmma::fragment<wmma::accumulator, 16, 16, 16, float> FragC;

// 3-term split MMA: acc[2][2] covers rows row0..+31, cols col0..+31.
__device__ __forceinline__ void gemm_chunk(const bf16* aH, const bf16* aL,
                                           const bf16* bH, const bf16* bL,
                                           int ksteps, FragC (&acc)[2][2],
                                           int row0, int col0)
{
    for (int ks = 0; ks < ksteps; ++ks) {
        FragA faH[2], faL[2];
        FragB fbH[2], fbL[2];
#pragma unroll
        for (int i = 0; i < 2; ++i) {
            wmma::load_matrix_sync(faH[i], aH + (row0 + 16 * i) * PA + ks * 16, PA);
            wmma::load_matrix_sync(faL[i], aL + (row0 + 16 * i) * PA + ks * 16, PA);
        }
#pragma unroll
        for (int j = 0; j < 2; ++j) {
            wmma::load_matrix_sync(fbH[j], bH + (ks * 16) * PW + col0 + 16 * j, PW);
            wmma::load_matrix_sync(fbL[j], bL + (ks * 16) * PW + col0 + 16 * j, PW);
        }
#pragma unroll
        for (int i = 0; i < 2; ++i)
#pragma unroll
            for (int j = 0; j < 2; ++j) {
                wmma::mma_sync(acc[i][j], faH[i], fbH[j], acc[i][j]);
                wmma::mma_sync(acc[i][j], faH[i], fbL[j], acc[i][j]);
                wmma::mma_sync(acc[i][j], faL[i], fbH[j], acc[i][j]);
            }
    }
}

// warp-local epilogue (no block barrier): store acc to warp-private cbuf patch,
// each lane processes one row: bias+silu+hi/lo split -> act tiles.
__device__ __forceinline__ void epi_warp(FragC (&acc)[2][2], float* __restrict__ cbuf,
                                         const float* __restrict__ bias,
                                         bf16* __restrict__ actH, bf16* __restrict__ actL,
                                         int lane, int row0, int col0)
{
#pragma unroll
    for (int i = 0; i < 2; ++i)
#pragma unroll
        for (int j = 0; j < 2; ++j)
            wmma::store_matrix_sync(cbuf + (row0 + 16 * i) * PC + col0 + 16 * j,
                                    acc[i][j], PC, wmma::mem_row_major);
    __syncwarp();
    const int r = row0 + lane;
    const float* crow = cbuf + r * PC;
#pragma unroll
    for (int c4 = 0; c4 < 32; c4 += 4) {
        int c = col0 + c4;
        float4 v = *(const float4*)&crow[c];
        float s0 = silu_f(v.x + bias[c]);
        float s1 = silu_f(v.y + bias[c + 1]);
        float s2 = silu_f(v.z + bias[c + 2]);
        float s3 = silu_f(v.w + bias[c + 3]);
        __nv_bfloat162 h0 = __floats2bfloat162_rn(s0, s1);
        __nv_bfloat162 l0 = __floats2bfloat162_rn(s0 - __low2float(h0), s1 - __high2float(h0));
        __nv_bfloat162 h1 = __floats2bfloat162_rn(s2, s3);
        __nv_bfloat162 l1 = __floats2bfloat162_rn(s2 - __low2float(h1), s3 - __high2float(h1));
        uint2 hv, lv;
        hv.x = *(uint32_t*)&h0; hv.y = *(uint32_t*)&h1;
        lv.x = *(uint32_t*)&l0; lv.y = *(uint32_t*)&l1;
        *(uint2*)&actH[r * PA + c] = hv;
        *(uint2*)&actL[r * PA + c] = lv;
    }
}

// ================= precompute: U[l] = ctx @ W1c[l] + te @ W1t[l] =================
__global__ __launch_bounds__(NTP, 1)
void pre_ctxte(const float* __restrict__ ctx, const float* __restrict__ te)
{
    extern __shared__ char smem[];
    bf16* cH = (bf16*)(smem + PSM_CTX);
    bf16* cL = cH + ALO_P;
    bf16* tH = (bf16*)(smem + PSM_TE);
    bf16* tL = tH + ALO_P;
    bf16* wbA = (bf16*)(smem + PSM_WB);
    bf16* wbB = (bf16*)(smem + PSM_WB + WBUF_B);

    const int tid = threadIdx.x;
    const long long row0b = (long long)blockIdx.x * TBP;

    const int w = tid >> 5;
    const int wr = w >> 2, wc = w & 3;
    const int row0 = wr * 32, col0 = wc * 32;

    {
        const float* sc = ctx + row0b * HHV;
        const float* st = te + row0b * HHV;
        for (int i = tid; i < TBP * 64; i += NTP) {
            int r = i >> 6, c = (i & 63) * 2;
            float2 v = *(const float2*)&sc[r * HHV + c];
            split_store(cH + r * PA + c,     cL + r * PA + c,     v.x);
            split_store(cH + r * PA + c + 1, cL + r * PA + c + 1, v.y);
            float2 u = *(const float2*)&st[r * HHV + c];
            split_store(tH + r * PA + c,     tL + r * PA + c,     u.x);
            split_store(tH + r * PA + c + 1, tL + r * PA + c + 1, u.y);
        }
    }

    for (int l = 0; l < NL; ++l) {
        const bf16* wc_ = g_Wc + (size_t)l * E_C;
        const bf16* wt_ = g_Wt_ + (size_t)l * E_C;

        FragC acc[2][2];
#pragma unroll
        for (int i = 0; i < 2; ++i)
#pragma unroll
            for (int j = 0; j < 2; ++j) wmma::fill_fragment(acc[i][j], 0.0f);

        cpa(wbA, wc_, CB_MLP, tid, NTP);
        cpa(wbB, wc_ + CHW_ELEM, CB_MLP, tid, NTP);
        __pipeline_wait_prior(1); __syncthreads();
        gemm_chunk(cH, cL, wbA, wbA + 64 * PW, 4, acc, row0, col0);
        __syncthreads();
        cpa(wbA, wt_, CB_MLP, tid, NTP);
        __pipeline_wait_prior(1); __syncthreads();
        gemm_chunk(cH + 64, cL + 64, wbB, wbB + 64 * PW, 4, acc, row0, col0);
        __syncthreads();
        cpa(wbB, wt_ + CHW_ELEM, CB_MLP, tid, NTP);
        __pipeline_wait_prior(1); __syncthreads();
        gemm_chunk(tH, tL, wbA, wbA + 64 * PW, 4, acc, row0, col0);
        __pipeline_wait_prior(0); __syncthreads();
        gemm_chunk(tH + 64, tL + 64, wbB, wbB + 64 * PW, 4, acc, row0, col0);
        __syncthreads();

        float* Ubase = g_U + ((size_t)l * BATCH + row0b) * HHV;
#pragma unroll
        for (int i = 0; i < 2; ++i)
#pragma unroll
            for (int j = 0; j < 2; ++j)
                wmma::store_matrix_sync(Ubase + (size_t)(row0 + 16 * i) * HHV + col0 + 16 * j,
                                        acc[i][j], HHV, wmma::mem_row_major);
    }
}

// ================= flow kernel: 64-row tiles, 2 blocks/SM =================
__global__ __launch_bounds__(NT, 2)
void biflow_wmma(const float* __restrict__ x,
                 const float* __restrict__ b1,
                 const float* __restrict__ b2,
                 const float* __restrict__ b3,
                 const float* __restrict__ bs,
                 const float* __restrict__ bt,
                 const int*   __restrict__ perm,
                 const int*   __restrict__ idx_a,
                 const int*   __restrict__ idx_b,
                 float* __restrict__ out)
{
    extern __shared__ char smem[];
    bf16*  actH = (bf16*)(smem + SM_ACT);
    bf16*  actL = actH + ALO_F;
    bf16*  wb   = (bf16*)(smem + SM_WB);
    float* cbuf = (float*)(smem + SM_CB);
    float* zt   = (float*)(smem + SM_ZT);
    float* ldet = (float*)(smem + SM_LDET);
    short* sa_s = (short*)(smem + SM_IDX);
    short* sb_s = sa_s + NL * ADIMV;
    short* da_s = sb_s + NL * ADIMV;
    short* db_s = da_s + NL * ADIMV;

    const int tid  = threadIdx.x;
    const int row0b = blockIdx.x * TB;

    // ---- init ----
    for (int idx = tid; idx < TB * DIMV; idx += NT) {
        int r = idx / DIMV, c = idx % DIMV;
        zt[r * ZP + c] = x[(long long)(row0b + r) * DIMV + c];
    }
    if (tid < TB) ldet[tid] = 0.0f;
    if (tid < NL * ADIMV) {
        int l = tid / ADIMV;
        int ia = idx_a[tid], ib = idx_b[tid];
        da_s[tid] = (short)ia; db_s[tid] = (short)ib;
        sa_s[tid] = (short)perm[l * DIMV + ia];
        sb_s[tid] = (short)perm[l * DIMV + ib];
    }
    __syncthreads();

    const int w = tid >> 5, lane = tid & 31;
    const int wr = w >> 2, wc = w & 3;
    const int row0 = wr * 32, col0 = wc * 32, col0h = wc * 16;

    for (int l = 0; l < NL; ++l) {
        const bf16* wza = g_Wza + (size_t)l * E_ZA;
        const bf16* w2  = g_W2 + (size_t)l * E_C;
        const bf16* w3  = g_W3 + (size_t)l * E_C;
        const bf16* whd = g_Whd + (size_t)l * E_HD;

        FragC acc[2][2];

        // ---- GEMM1: prefetch za weights; load U; build za act ----
        cpa(wb, wza, CB_ZA, tid, NT);
        {
            const float* Ubase = g_U + ((size_t)l * BATCH + row0b) * HHV;
#pragma unroll
            for (int i = 0; i < 2; ++i)
#pragma unroll
                for (int j = 0; j < 2; ++j)
                    wmma::load_matrix_sync(acc[i][j],
                        Ubase + (size_t)(row0 + 16 * i) * HHV + col0 + 16 * j,
                        HHV, wmma::mem_row_major);
        }
        for (int i = tid; i < TB * 32; i += NT) {
            int r = i >> 5, k = i & 31;
            float v = (k < ADIMV) ? zt[r * ZP + sa_s[l * ADIMV + k]] : 0.0f;
            split_store(actH + r * PA + k, actL + r * PA + k, v);
        }
        __pipeline_wait_prior(0); __syncthreads();     // za weights + act ready
        gemm_chunk(actH, actL, wb, wb + 32 * PA, 2, acc, row0, col0);
        __syncthreads();                               // wb free, act reads done
        cpa(wb, w2, CB_MLP, tid, NT);                  // W2c0
        epi_warp(acc, cbuf, b1 + l * HHV, actH, actL, lane, row0, col0);  // h1 -> act

        // ---- GEMM2 ----
#pragma unroll
        for (int i = 0; i < 2; ++i)
#pragma unroll
            for (int j = 0; j < 2; ++j) wmma::fill_fragment(acc[i][j], 0.0f);
        __pipeline_wait_prior(0); __syncthreads();     // W2c0 + h1 complete
        gemm_chunk(actH, actL, wb, wb + 64 * PW, 4, acc, row0, col0);
        __syncthreads();                               // wb free
        cpa(wb, w2 + CHW_ELEM, CB_MLP, tid, NT);       // W2c1
        __pipeline_wait_prior(0); __syncthreads();
        gemm_chunk(actH + 64, actL + 64, wb, wb + 64 * PW, 4, acc, row0, col0);
        __syncthreads();                               // wb free, h1 reads done
        cpa(wb, w3, CB_MLP, tid, NT);                  // W3c0
        epi_warp(acc, cbuf, b2 + l * HHV, actH, actL, lane, row0, col0);  // h2 -> act

        // ---- GEMM3 ----
#pragma unroll
        for (int i = 0; i < 2; ++i)
#pragma unroll
            for (int j = 0; j < 2; ++j) wmma::fill_fragment(acc[i][j], 0.0f);
        __pipeline_wait_prior(0); __syncthreads();     // W3c0 + h2 complete
        gemm_chunk(actH, actL, wb, wb + 64 * PW, 4, acc, row0, col0);
        __syncthreads();                               // wb free
        cpa(wb, w3 + CHW_ELEM, CB_MLP, tid, NT);       // W3c1
        __pipeline_wait_prior(0); __syncthreads();
        gemm_chunk(actH + 64, actL + 64, wb, wb + 64 * PW, 4, acc, row0, col0);
        __syncthreads();                               // wb free, h2 reads done
        cpa(wb, whd, CB_HD, tid, NT);                  // HDc0
        epi_warp(acc, cbuf, b3 + l * HHV, actH, actL, lane, row0, col0);  // h3 -> act

        // ---- heads ----
        {
            FragC acc2[2];
            wmma::fill_fragment(acc2[0], 0.0f);
            wmma::fill_fragment(acc2[1], 0.0f);
            __pipeline_wait_prior(0); __syncthreads(); // HDc0 + h3 complete
            for (int q = 0; q < 2; ++q) {
                const bf16* bH = wb;
                const bf16* bL = wb + 64 * PH;
                const bf16* aHq = actH + q * 64;
                const bf16* aLq = actL + q * 64;
                for (int ks = 0; ks < 4; ++ks) {
                    FragA faH[2], faL[2];
                    FragB fbH, fbL;
#pragma unroll
                    for (int i = 0; i < 2; ++i) {
                        wmma::load_matrix_sync(faH[i], aHq + (row0 + 16 * i) * PA + ks * 16, PA);
                        wmma::load_matrix_sync(faL[i], aLq + (row0 + 16 * i) * PA + ks * 16, PA);
                    }
                    wmma::load_matrix_sync(fbH, bH + (ks * 16) * PH + col0h, PH);
                    wmma::load_matrix_sync(fbL, bL + (ks * 16) * PH + col0h, PH);
#pragma unroll
                    for (int i = 0; i < 2; ++i) {
                        wmma::mma_sync(acc2[i], faH[i], fbH, acc2[i]);
                        wmma::mma_sync(acc2[i], faH[i], fbL, acc2[i]);
                        wmma::mma_sync(acc2[i], faL[i], fbH, acc2[i]);
                    }
                }
                if (q == 0) {
                    __syncthreads();                   // wb free
                    cpa(wb, whd + CHH_ELEM, CB_HD, tid, NT);   // HDc1
                    __pipeline_wait_prior(0); __syncthreads();
                }
            }
#pragma unroll
            for (int i = 0; i < 2; ++i)
                wmma::store_matrix_sync(cbuf + (row0 + 16 * i) * PCH + col0h,
                                        acc2[i], PCH, wmma::mem_row_major);
            __syncthreads();
        }

        // ---- coupling: TB threads, each owns one row ----
        if (tid < TB) {
            float sv[ADIMV], tv[ADIMV];
#pragma unroll
            for (int j = 0; j < ADIMV; ++j) {
                float s = cbuf[tid * PCH + j] + bs[l * ADIMV + j];
                sv[j] = fminf(fmaxf(s, -CLIPV), CLIPV);
                tv[j] = cbuf[tid * PCH + ADIMV + j] + bt[l * ADIMV + j];
            }
            float zan[ADIMV], ybn[ADIMV], lsum = 0.0f;
#pragma unroll
            for (int j = 0; j < ADIMV; ++j) {
                float zb = zt[tid * ZP + sb_s[l * ADIMV + j]];
                ybn[j] = fmaf(zb, __expf(sv[j]), tv[j]);
                zan[j] = zt[tid * ZP + sa_s[l * ADIMV + j]];
                lsum += sv[j];
            }
#pragma unroll
            for (int j = 0; j < ADIMV; ++j) {
                zt[tid * ZP + da_s[l * ADIMV + j]] = zan[j];
                zt[tid * ZP + db_s[l * ADIMV + j]] = ybn[j];
            }
            ldet[tid] += lsum;
        }
        __syncthreads();
    }

    // ---- output: z (B x 40) then logdet (B) ----
    for (int idx = tid; idx < TB * DIMV; idx += NT) {
        int r = idx / DIMV, c = idx % DIMV;
        out[(long long)(row0b + r) * DIMV + c] = zt[r * ZP + c];
    }
    if (tid < TB)
        out[(long long)BATCH * DIMV + row0b + tid] = ldet[tid];
}

extern "C" void kernel_launch(void* const* d_in, const int* in_sizes, int n_in,
                              void* d_out, int out_size) {
    const float* x    = (const float*)d_in[0];
    const float* ctx  = (const float*)d_in[1];
    const float* te   = (const float*)d_in[2];
    const float* W1   = (const float*)d_in[3];
    const float* b1   = (const float*)d_in[4];
    const float* W2   = (const float*)d_in[5];
    const float* b2   = (const float*)d_in[6];
    const float* W3   = (const float*)d_in[7];
    const float* b3   = (const float*)d_in[8];
    const float* Ws   = (const float*)d_in[9];
    const float* bs   = (const float*)d_in[10];
    const float* Wt   = (const float*)d_in[11];
    const float* bt   = (const float*)d_in[12];
    const int*   perm = (const int*)d_in[13];
    const int*   ia   = (const int*)d_in[14];
    const int*   ib   = (const int*)d_in[15];
    float* out = (float*)d_out;

    prep_weights<<<512, 256>>>(W1, W2, W3, Ws, Wt);

    cudaFuncSetAttribute(pre_ctxte,
                         cudaFuncAttributeMaxDynamicSharedMemorySize, SMEM_PRE);
    pre_ctxte<<<BATCH / TBP, NTP, SMEM_PRE>>>(ctx, te);

    cudaFuncSetAttribute(biflow_wmma,
                         cudaFuncAttributeMaxDynamicSharedMemorySize, SMEM_TOTAL);
    biflow_wmma<<<BATCH / TB, NT, SMEM_TOTAL>>>(
        x, b1, b2, b3, bs, bt, perm, ia, ib, out);
}